// round 9
// baseline (speedup 1.0000x reference)
#include <cuda_runtime.h>
#include <cuda_bf16.h>
#include <cstdint>

#define NN 50000
#define NE 312500
#define NG 50
#define DIN 384
#define DH 256
#define DOUT 256

// ---- scratch (allocation-free: __device__ globals) ----
__device__ float g_h[(size_t)NN * DH];
__device__ float g_e[(size_t)NE * DH];
__device__ float g_aggr[(size_t)NN * DH];
__device__ float g_t[(size_t)NN * DH];
__device__ float g_pool[NG * DH];
__device__ float g_cnt[NG];
__device__ int   g_root[NG];
__device__ int   g_src[NE];
__device__ int   g_dst[NE];
__device__ int   g_batch[NN];
__device__ int   g_is64;

// transposed + hi/lo-split weights: [N=256, K] bf16, K-major rows
#define WT_TOTAL 458752
__device__ __nv_bfloat16 g_whi[WT_TOTAL];
__device__ __nv_bfloat16 g_wlo[WT_TOTAL];

// ============================================================
// baseline-PTX tensor helpers (sm_80 features; OK at compute_103)
// ============================================================
__device__ __forceinline__ void ldsm_x4(uint32_t& r0, uint32_t& r1, uint32_t& r2, uint32_t& r3,
                                        uint32_t addr) {
    asm volatile("ldmatrix.sync.aligned.m8n8.x4.shared.b16 {%0,%1,%2,%3}, [%4];"
                 : "=r"(r0), "=r"(r1), "=r"(r2), "=r"(r3) : "r"(addr));
}
__device__ __forceinline__ void mma16816(float* c, const uint32_t* a, const uint32_t* b) {
    asm volatile(
        "mma.sync.aligned.m16n8k16.row.col.f32.bf16.bf16.f32 "
        "{%0,%1,%2,%3}, {%4,%5,%6,%7}, {%8,%9}, {%0,%1,%2,%3};"
        : "+f"(c[0]), "+f"(c[1]), "+f"(c[2]), "+f"(c[3])
        : "r"(a[0]), "r"(a[1]), "r"(a[2]), "r"(a[3]), "r"(b[0]), "r"(b[1]));
}
__device__ __forceinline__ void split2(float a, float b, uint32_t& hi, uint32_t& lo) {
    __nv_bfloat16 ha = __float2bfloat16(a), hb = __float2bfloat16(b);
    float ra = a - __bfloat162float(ha);
    float rb = b - __bfloat162float(hb);
    hi = (uint32_t)__bfloat16_as_ushort(ha) | ((uint32_t)__bfloat16_as_ushort(hb) << 16);
    lo = (uint32_t)__bfloat16_as_ushort(__float2bfloat16(ra)) |
         ((uint32_t)__bfloat16_as_ushort(__float2bfloat16(rb)) << 16);
}

// ============================================================
// dtype detection for int64-vs-int32 index buffers
// ============================================================
__global__ __launch_bounds__(1024) void detect_kernel(const unsigned* __restrict__ w)
{
    __shared__ unsigned red[32];
    unsigned acc = 0;
    for (int i = threadIdx.x; i < NE; i += 1024)
        acc |= w[2 * i + 1];
#pragma unroll
    for (int o = 16; o > 0; o >>= 1) acc |= __shfl_xor_sync(0xffffffffu, acc, o);
    if ((threadIdx.x & 31) == 0) red[threadIdx.x >> 5] = acc;
    __syncthreads();
    if (threadIdx.x < 32) {
        unsigned v = red[threadIdx.x];
#pragma unroll
        for (int o = 16; o > 0; o >>= 1) v |= __shfl_xor_sync(0xffffffffu, v, o);
        if (threadIdx.x == 0) g_is64 = (v == 0u) ? 1 : 0;
    }
}

__global__ void convert_idx_kernel(const void* __restrict__ ei, const void* __restrict__ batch)
{
    int i = blockIdx.x * blockDim.x + threadIdx.x;
    const int is64 = g_is64;
    if (i < NE) {
        long long s, d;
        if (is64) {
            s = ((const long long*)ei)[i];
            d = ((const long long*)ei)[NE + i];
        } else {
            s = ((const int*)ei)[i];
            d = ((const int*)ei)[NE + i];
        }
        g_src[i] = (int)min((long long)(NN - 1), max(0LL, s));
        g_dst[i] = (int)min((long long)(NN - 1), max(0LL, d));
    }
    if (i < NN) {
        long long b = is64 ? ((const long long*)batch)[i] : (long long)((const int*)batch)[i];
        g_batch[i] = (int)min((long long)(NG - 1), max(0LL, b));
    }
}

// ---- weight prep: W[K,256] fp32 -> Wt hi/lo [256,K] bf16 ----
__global__ void prep_w_kernel(const float* __restrict__ W, int K, int off)
{
    int idx = blockIdx.x * blockDim.x + threadIdx.x;
    if (idx >= K * 256) return;
    int k = idx >> 8, n = idx & 255;
    float w = W[idx];
    __nv_bfloat16 h = __float2bfloat16(w);
    float r = w - __bfloat162float(h);
    g_whi[off + n * K + k] = h;
    g_wlo[off + n * K + k] = __float2bfloat16(r);
}

// ============================================================
// bf16x2-split mma.sync GEMM, double-buffered register prefetch.
// C[M,256] = epi(A[M,K] @ W[K,256] + bias)
// C ≈ Ahi·Bhi + Ahi·Blo + Alo·Bhi  (fp32 accum)
// CTA 128x128, 256 threads, 8 warps (2x4), warp tile 64x32, BK=32.
// smem: 2 buffers x {Ah,Al,Bh,Bl}[128][40] bf16 = 81920 B dynamic.
// MODE 0: C=AB+b ; 1: relu ; 2: relu(AB+b+res) (res may alias C)
// ============================================================
#define TG_BUF_ELEMS 20480           // elems per buffer (4 arrays x 128 x 40)
#define TG_ARR_BYTES 10240           // bytes per array (128 x 40 x 2)
#define TG_SMEM_BYTES 81920

template <int MODE>
__global__ __launch_bounds__(256) void tgemm_kernel(
    const float* __restrict__ A,
    const __nv_bfloat16* __restrict__ Bh, const __nv_bfloat16* __restrict__ Bl,
    const float* __restrict__ bias, float* C, const float* res, int M, int K)
{
    extern __shared__ __nv_bfloat16 sm[];

    const int tid = threadIdx.x;
    const int lane = tid & 31, wid = tid >> 5;
    const int warp_m = wid >> 2, warp_n = wid & 3;   // 2 x 4 warp grid
    const int m0 = blockIdx.x * 128, n0 = blockIdx.y * 128;

    // loader coords: thread -> (row, k-half)
    const int lm  = tid >> 1;
    const int lkh = (tid & 1) * 16;

    // ldmatrix per-lane element coords
    const int a_r = lane & 15;
    const int a_c = (lane >> 4) << 3;
    const int b_r = ((lane >> 4) << 3) + (lane & 7);
    const int b_c = ((lane >> 3) & 1) << 3;

    const uint32_t u0 = (uint32_t)__cvta_generic_to_shared(sm);

    // prefetch registers
    uint32_t hh[8], ll[8];           // A hi/lo bf16x2
    uint4 vb[4];                     // B hi (2) + lo (2)

    const int gm_ld = m0 + lm;
    const float* aldp = A + (size_t)gm_ld * K + lkh;
    const __nv_bfloat16* bhp = Bh + (size_t)(n0 + lm) * K + lkh;
    const __nv_bfloat16* blp = Bl + (size_t)(n0 + lm) * K + lkh;

    auto load_regs = [&](int k0) {
        if (gm_ld < M) {
#pragma unroll
            for (int j = 0; j < 4; j++) {
                float4 v = *reinterpret_cast<const float4*>(aldp + k0 + j * 4);
                split2(v.x, v.y, hh[2 * j],     ll[2 * j]);
                split2(v.z, v.w, hh[2 * j + 1], ll[2 * j + 1]);
            }
        } else {
#pragma unroll
            for (int j = 0; j < 8; j++) { hh[j] = 0u; ll[j] = 0u; }
        }
        vb[0] = *reinterpret_cast<const uint4*>(bhp + k0);
        vb[1] = *reinterpret_cast<const uint4*>(bhp + k0 + 8);
        vb[2] = *reinterpret_cast<const uint4*>(blp + k0);
        vb[3] = *reinterpret_cast<const uint4*>(blp + k0 + 8);
    };
    auto store_smem = [&](int buf) {
        __nv_bfloat16* base = sm + buf * TG_BUF_ELEMS;
        uint32_t* dh = reinterpret_cast<uint32_t*>(base + lm * 40 + lkh);
        uint32_t* dl = reinterpret_cast<uint32_t*>(base + 5120 + lm * 40 + lkh);
        *reinterpret_cast<uint4*>(dh)     = make_uint4(hh[0], hh[1], hh[2], hh[3]);
        *reinterpret_cast<uint4*>(dh + 4) = make_uint4(hh[4], hh[5], hh[6], hh[7]);
        *reinterpret_cast<uint4*>(dl)     = make_uint4(ll[0], ll[1], ll[2], ll[3]);
        *reinterpret_cast<uint4*>(dl + 4) = make_uint4(ll[4], ll[5], ll[6], ll[7]);
        *reinterpret_cast<uint4*>(base + 10240 + lm * 40 + lkh)     = vb[0];
        *reinterpret_cast<uint4*>(base + 10240 + lm * 40 + lkh + 8) = vb[1];
        *reinterpret_cast<uint4*>(base + 15360 + lm * 40 + lkh)     = vb[2];
        *reinterpret_cast<uint4*>(base + 15360 + lm * 40 + lkh + 8) = vb[3];
    };

    float acc[4][4][4];
#pragma unroll
    for (int i = 0; i < 4; i++)
#pragma unroll
        for (int j = 0; j < 4; j++)
#pragma unroll
            for (int q = 0; q < 4; q++) acc[i][j][q] = 0.f;

    load_regs(0);
    store_smem(0);
    __syncthreads();

    int buf = 0;
    const int ntiles = K >> 5;
    for (int kt = 0; kt < ntiles; kt++) {
        const bool has_next = (kt + 1) < ntiles;
        if (has_next) load_regs((kt + 1) << 5);   // overlap with MMAs below

        const uint32_t uAh = u0 + buf * (TG_BUF_ELEMS * 2);
        const uint32_t uAl = uAh + TG_ARR_BYTES;
        const uint32_t uBh = uAh + 2 * TG_ARR_BYTES;
        const uint32_t uBl = uAh + 3 * TG_ARR_BYTES;

#pragma unroll
        for (int ks = 0; ks < 2; ks++) {
            uint32_t ah[4][4], al[4][4], bh[4][2], bl[4][2];
#pragma unroll
            for (int mt = 0; mt < 4; mt++) {
                int r = warp_m * 64 + mt * 16 + a_r;
                int c = ks * 16 + a_c;
                uint32_t off = (uint32_t)(r * 40 + c) * 2;
                ldsm_x4(ah[mt][0], ah[mt][1], ah[mt][2], ah[mt][3], uAh + off);
                ldsm_x4(al[mt][0], al[mt][1], al[mt][2], al[mt][3], uAl + off);
            }
#pragma unroll
            for (int np = 0; np < 2; np++) {
                int r = warp_n * 32 + np * 16 + b_r;
                int c = ks * 16 + b_c;
                uint32_t off = (uint32_t)(r * 40 + c) * 2;
                uint32_t r0, r1, r2, r3;
                ldsm_x4(r0, r1, r2, r3, uBh + off);
                bh[2 * np][0] = r0; bh[2 * np][1] = r1;
                bh[2 * np + 1][0] = r2; bh[2 * np + 1][1] = r3;
                ldsm_x4(r0, r1, r2, r3, uBl + off);
                bl[2 * np][0] = r0; bl[2 * np][1] = r1;
                bl[2 * np + 1][0] = r2; bl[2 * np + 1][1] = r3;
            }
#pragma unroll
            for (int mt = 0; mt < 4; mt++)
#pragma unroll
                for (int nt = 0; nt < 4; nt++) {
                    mma16816(acc[mt][nt], ah[mt], bh[nt]);
                    mma16816(acc[mt][nt], ah[mt], bl[nt]);
                    mma16816(acc[mt][nt], al[mt], bh[nt]);
                }
        }

        if (has_next) {
            store_smem(buf ^ 1);
            __syncthreads();
            buf ^= 1;
        }
    }

    // ---- epilogue ----
#pragma unroll
    for (int nt = 0; nt < 4; nt++) {
        const int gn = n0 + warp_n * 32 + nt * 8 + (lane & 3) * 2;
        const float b0 = bias[gn], b1 = bias[gn + 1];
#pragma unroll
        for (int mt = 0; mt < 4; mt++) {
            const int gm = m0 + warp_m * 64 + mt * 16 + (lane >> 2);
#pragma unroll
            for (int half = 0; half < 2; half++) {
                const int r = gm + half * 8;
                if (r < M) {
                    float x0 = acc[mt][nt][2 * half]     + b0;
                    float x1 = acc[mt][nt][2 * half + 1] + b1;
                    size_t base = (size_t)r * 256 + gn;
                    if (MODE == 2) { x0 += res[base]; x1 += res[base + 1]; }
                    if (MODE >= 1) { x0 = fmaxf(x0, 0.f); x1 = fmaxf(x1, 0.f); }
                    *reinterpret_cast<float2*>(&C[base]) = make_float2(x0, x1);
                }
            }
        }
    }
}

// ============================================================
// message + scatter: aggr[dst] += relu(h[src] + e), warp per edge
// ============================================================
__global__ __launch_bounds__(256) void message_kernel(
    const float* __restrict__ h, const float* __restrict__ e,
    float* __restrict__ aggr)
{
    int warp = (blockIdx.x * blockDim.x + threadIdx.x) >> 5;
    int lane = threadIdx.x & 31;
    if (warp >= NE) return;
    int s = g_src[warp];
    int d = g_dst[warp];
    const float4* hs = reinterpret_cast<const float4*>(h + (size_t)s * DH);
    const float4* es = reinterpret_cast<const float4*>(e + (size_t)warp * DH);
    float* ad = aggr + (size_t)d * DH;
#pragma unroll
    for (int i = 0; i < 2; i++) {
        int f = lane + i * 32;
        float4 hv = hs[f];
        float4 ev = es[f];
        float mx = fmaxf(hv.x + ev.x, 0.f);
        float my = fmaxf(hv.y + ev.y, 0.f);
        float mz = fmaxf(hv.z + ev.z, 0.f);
        float mw = fmaxf(hv.w + ev.w, 0.f);
        asm volatile("red.global.add.v4.f32 [%0], {%1,%2,%3,%4};"
                     :: "l"(ad + (size_t)f * 4), "f"(mx), "f"(my), "f"(mz), "f"(mw)
                     : "memory");
    }
}

__global__ void init_z_kernel(const float* __restrict__ h, const float* __restrict__ eps,
                              float* __restrict__ aggr)
{
    size_t i = (size_t)blockIdx.x * blockDim.x + threadIdx.x;
    size_t n = (size_t)NN * DH / 4;
    if (i >= n) return;
    float s = 1.0f + *eps;
    float4 hv = reinterpret_cast<const float4*>(h)[i];
    reinterpret_cast<float4*>(aggr)[i] =
        make_float4(s * hv.x, s * hv.y, s * hv.z, s * hv.w);
}

__global__ void zero_pc_kernel(float* __restrict__ pool, float* __restrict__ cnt)
{
    int i = blockIdx.x * blockDim.x + threadIdx.x;
    if (i < NG * DH) pool[i] = 0.f;
    if (i < NG) cnt[i] = 0.f;
}

// ---- pooling: batch is sorted; run-length accumulate, few atomics ----
__global__ __launch_bounds__(256) void pool_kernel(
    const float* __restrict__ h, float* __restrict__ pool, float* __restrict__ cnt)
{
    const int f = threadIdx.x;
    int start = blockIdx.x * 100;
    int end = start + 100;
    if (end > NN) end = NN;
    if (start >= NN) return;
    float acc = 0.f;
    int cur = g_batch[start];
    int runlen = 0;
    for (int i = start; i < end; i++) {
        int b = g_batch[i];
        if (b != cur) {
            atomicAdd(&pool[cur * DH + f], acc);
            if (f == 0) atomicAdd(&cnt[cur], (float)runlen);
            acc = 0.f; runlen = 0; cur = b;
        }
        acc += h[(size_t)i * DH + f];
        runlen++;
    }
    atomicAdd(&pool[cur * DH + f], acc);
    if (f == 0) atomicAdd(&cnt[cur], (float)runlen);
}

__global__ void root_kernel(int* __restrict__ root)
{
    int i = blockIdx.x * blockDim.x + threadIdx.x;
    if (i >= NN) return;
    int b = g_batch[i];
    if (i == 0 || g_batch[i - 1] != b) root[b] = i;
}

__global__ __launch_bounds__(256) void final_kernel(
    const float* __restrict__ h, const float* __restrict__ pool,
    const float* __restrict__ cnt, const int* __restrict__ root,
    const float* __restrict__ Wo, const float* __restrict__ bo,
    const float* __restrict__ alpha, float* __restrict__ out)
{
    __shared__ float vec[DH];
    int g = blockIdx.x;
    int t = threadIdx.x;
    float a = *alpha;
    vec[t] = pool[g * DH + t] / cnt[g] + a * h[(size_t)root[g] * DH + t];
    __syncthreads();
    float s = bo[t];
#pragma unroll 8
    for (int k = 0; k < DH; k++) s = fmaf(vec[k], Wo[k * DOUT + t], s);
    out[g * DOUT + t] = s;
}

// ============================================================
extern "C" void kernel_launch(void* const* d_in, const int* in_sizes, int n_in,
                              void* d_out, int out_size)
{
    const float* x    = (const float*)d_in[0];
    const float* ea   = (const float*)d_in[1];
    const float* Wn   = (const float*)d_in[2];
    const float* bn   = (const float*)d_in[3];
    const float* We   = (const float*)d_in[4];
    const float* be   = (const float*)d_in[5];
    const float* c1W1 = (const float*)d_in[6];
    const float* c1b1 = (const float*)d_in[7];
    const float* c1W2 = (const float*)d_in[8];
    const float* c1b2 = (const float*)d_in[9];
    const float* eps1 = (const float*)d_in[10];
    const float* c2W1 = (const float*)d_in[11];
    const float* c2b1 = (const float*)d_in[12];
    const float* c2W2 = (const float*)d_in[13];
    const float* c2b2 = (const float*)d_in[14];
    const float* eps2 = (const float*)d_in[15];
    const float* Wo   = (const float*)d_in[16];
    const float* bo   = (const float*)d_in[17];
    const float* alpha= (const float*)d_in[18];
    const void*  ei    = d_in[19];
    const void*  batch = d_in[20];
    float* out = (float*)d_out;

    float *ph, *pe, *pa, *pt, *ppool, *pcnt;
    int* proot;
    __nv_bfloat16 *pwh, *pwl;
    cudaGetSymbolAddress((void**)&ph, g_h);
    cudaGetSymbolAddress((void**)&pe, g_e);
    cudaGetSymbolAddress((void**)&pa, g_aggr);
    cudaGetSymbolAddress((void**)&pt, g_t);
    cudaGetSymbolAddress((void**)&ppool, g_pool);
    cudaGetSymbolAddress((void**)&pcnt, g_cnt);
    cudaGetSymbolAddress((void**)&proot, g_root);
    cudaGetSymbolAddress((void**)&pwh, g_whi);
    cudaGetSymbolAddress((void**)&pwl, g_wlo);

    cudaFuncSetAttribute(tgemm_kernel<0>, cudaFuncAttributeMaxDynamicSharedMemorySize, TG_SMEM_BYTES);
    cudaFuncSetAttribute(tgemm_kernel<1>, cudaFuncAttributeMaxDynamicSharedMemorySize, TG_SMEM_BYTES);
    cudaFuncSetAttribute(tgemm_kernel<2>, cudaFuncAttributeMaxDynamicSharedMemorySize, TG_SMEM_BYTES);

    const dim3 gridN((NN + 127) / 128, 2);
    const dim3 gridE((NE + 127) / 128, 2);
    const size_t nh4 = (size_t)NN * DH / 4;
    const int zblocks = (int)((nh4 + 255) / 256);

    // index dtype detection + conversion
    detect_kernel<<<1, 1024>>>((const unsigned*)ei);
    convert_idx_kernel<<<(NE + 255) / 256, 256>>>(ei, batch);

    // weight prep: transpose + hi/lo split
    const int O_WN = 0, O_WE = 98304, O_11 = 196608, O_12 = 262144, O_21 = 327680, O_22 = 393216;
    prep_w_kernel<<<(DIN * 256 + 255) / 256, 256>>>(Wn,   DIN, O_WN);
    prep_w_kernel<<<(DIN * 256 + 255) / 256, 256>>>(We,   DIN, O_WE);
    prep_w_kernel<<<(DH  * 256 + 255) / 256, 256>>>(c1W1, DH,  O_11);
    prep_w_kernel<<<(DH  * 256 + 255) / 256, 256>>>(c1W2, DH,  O_12);
    prep_w_kernel<<<(DH  * 256 + 255) / 256, 256>>>(c2W1, DH,  O_21);
    prep_w_kernel<<<(DH  * 256 + 255) / 256, 256>>>(c2W2, DH,  O_22);

    // projections (tensor cores via mma.sync)
    tgemm_kernel<0><<<gridN, 256, TG_SMEM_BYTES>>>(x,  pwh + O_WN, pwl + O_WN, bn, ph, nullptr, NN, DIN);
    tgemm_kernel<0><<<gridE, 256, TG_SMEM_BYTES>>>(ea, pwh + O_WE, pwl + O_WE, be, pe, nullptr, NE, DIN);

    // two GINE layers
    for (int layer = 0; layer < 2; layer++) {
        const float* b1 = layer ? c2b1 : c1b1;
        const float* b2 = layer ? c2b2 : c1b2;
        const float* ep = layer ? eps2 : eps1;
        const int o1 = layer ? O_21 : O_11;
        const int o2 = layer ? O_22 : O_12;

        init_z_kernel<<<zblocks, 256>>>(ph, ep, pa);
        message_kernel<<<(NE * 32 + 255) / 256, 256>>>(ph, pe, pa);
        tgemm_kernel<1><<<gridN, 256, TG_SMEM_BYTES>>>(pa, pwh + o1, pwl + o1, b1, pt, nullptr, NN, DH);
        tgemm_kernel<2><<<gridN, 256, TG_SMEM_BYTES>>>(pt, pwh + o2, pwl + o2, b2, ph, ph, NN, DH);
    }

    // pooling + head
    zero_pc_kernel<<<(NG * DH + 255) / 256, 256>>>(ppool, pcnt);
    pool_kernel<<<(NN + 99) / 100, 256>>>(ph, ppool, pcnt);
    root_kernel<<<(NN + 255) / 256, 256>>>(proot);
    final_kernel<<<NG, 256>>>(ph, ppool, pcnt, proot, Wo, bo, alpha, out);
}

// round 15
// speedup vs baseline: 1.1320x; 1.1320x over previous
#include <cuda_runtime.h>
#include <cuda_bf16.h>
#include <cstdint>

#define NN 50000
#define NE 312500
#define NG 50
#define DIN 384
#define DH 256
#define DOUT 256

// ---- scratch (allocation-free: __device__ globals) ----
__device__ float g_h[(size_t)NN * DH];
__device__ float g_e[(size_t)NE * DH];
__device__ float g_aggr[(size_t)NN * DH];
__device__ float g_t[(size_t)NN * DH];
__device__ float g_pool[NG * DH];
__device__ float g_cnt[NG];
__device__ int   g_root[NG];
__device__ int   g_src[NE];
__device__ int   g_dst[NE];
__device__ int   g_batch[NN];
__device__ int   g_is64;

// transposed + hi/lo-split weights: [N=256, K] bf16, K-major rows
#define WT_TOTAL 458752
__device__ __nv_bfloat16 g_whi[WT_TOTAL];
__device__ __nv_bfloat16 g_wlo[WT_TOTAL];

// ============================================================
// baseline-PTX tensor / async helpers (sm_80 features; OK at compute_103)
// ============================================================
__device__ __forceinline__ void ldsm_x4(uint32_t& r0, uint32_t& r1, uint32_t& r2, uint32_t& r3,
                                        uint32_t addr) {
    asm volatile("ldmatrix.sync.aligned.m8n8.x4.shared.b16 {%0,%1,%2,%3}, [%4];"
                 : "=r"(r0), "=r"(r1), "=r"(r2), "=r"(r3) : "r"(addr));
}
__device__ __forceinline__ void mma16816(float* c, const uint32_t* a, const uint32_t* b) {
    asm volatile(
        "mma.sync.aligned.m16n8k16.row.col.f32.bf16.bf16.f32 "
        "{%0,%1,%2,%3}, {%4,%5,%6,%7}, {%8,%9}, {%0,%1,%2,%3};"
        : "+f"(c[0]), "+f"(c[1]), "+f"(c[2]), "+f"(c[3])
        : "r"(a[0]), "r"(a[1]), "r"(a[2]), "r"(a[3]), "r"(b[0]), "r"(b[1]));
}
__device__ __forceinline__ void split2(float a, float b, uint32_t& hi, uint32_t& lo) {
    __nv_bfloat16 ha = __float2bfloat16(a), hb = __float2bfloat16(b);
    float ra = a - __bfloat162float(ha);
    float rb = b - __bfloat162float(hb);
    hi = (uint32_t)__bfloat16_as_ushort(ha) | ((uint32_t)__bfloat16_as_ushort(hb) << 16);
    lo = (uint32_t)__bfloat16_as_ushort(__float2bfloat16(ra)) |
         ((uint32_t)__bfloat16_as_ushort(__float2bfloat16(rb)) << 16);
}
__device__ __forceinline__ void cpa16(uint32_t dst, const void* src, int srcsize) {
    asm volatile("cp.async.cg.shared.global [%0], [%1], 16, %2;"
                 :: "r"(dst), "l"(src), "r"(srcsize) : "memory");
}
__device__ __forceinline__ void cpa_commit() {
    asm volatile("cp.async.commit_group;" ::: "memory");
}

// ============================================================
// dtype detection for int64-vs-int32 index buffers
// ============================================================
__global__ __launch_bounds__(1024) void detect_kernel(const unsigned* __restrict__ w)
{
    __shared__ unsigned red[32];
    unsigned acc = 0;
    for (int i = threadIdx.x; i < NE; i += 1024)
        acc |= w[2 * i + 1];
#pragma unroll
    for (int o = 16; o > 0; o >>= 1) acc |= __shfl_xor_sync(0xffffffffu, acc, o);
    if ((threadIdx.x & 31) == 0) red[threadIdx.x >> 5] = acc;
    __syncthreads();
    if (threadIdx.x < 32) {
        unsigned v = red[threadIdx.x];
#pragma unroll
        for (int o = 16; o > 0; o >>= 1) v |= __shfl_xor_sync(0xffffffffu, v, o);
        if (threadIdx.x == 0) g_is64 = (v == 0u) ? 1 : 0;
    }
}

__global__ void convert_idx_kernel(const void* __restrict__ ei, const void* __restrict__ batch)
{
    int i = blockIdx.x * blockDim.x + threadIdx.x;
    const int is64 = g_is64;
    if (i < NE) {
        long long s, d;
        if (is64) {
            s = ((const long long*)ei)[i];
            d = ((const long long*)ei)[NE + i];
        } else {
            s = ((const int*)ei)[i];
            d = ((const int*)ei)[NE + i];
        }
        g_src[i] = (int)min((long long)(NN - 1), max(0LL, s));
        g_dst[i] = (int)min((long long)(NN - 1), max(0LL, d));
    }
    if (i < NN) {
        long long b = is64 ? ((const long long*)batch)[i] : (long long)((const int*)batch)[i];
        g_batch[i] = (int)min((long long)(NG - 1), max(0LL, b));
    }
}

// ---- weight prep: W[K,256] fp32 -> Wt hi/lo [256,K] bf16 ----
__global__ void prep_w_kernel(const float* __restrict__ W, int K, int off)
{
    int idx = blockIdx.x * blockDim.x + threadIdx.x;
    if (idx >= K * 256) return;
    int k = idx >> 8, n = idx & 255;
    float w = W[idx];
    __nv_bfloat16 h = __float2bfloat16(w);
    float r = w - __bfloat162float(h);
    g_whi[off + n * K + k] = h;
    g_wlo[off + n * K + k] = __float2bfloat16(r);
}

// ============================================================
// bf16x2-split mma.sync GEMM with cp.async double-buffered staging.
// Race-free schedule: issue(kt+2) only AFTER the post-MMA barrier, so
// no warp can still be reading staging[buf] when it is overwritten.
// Tile kt+1 stays in flight during tile kt's MMAs (depth-2 pipeline).
// C[M,256] = epi(A[M,K] @ W[K,256] + bias)
// C ≈ Ahi·Bhi + Ahi·Blo + Alo·Bhi  (fp32 accum)
// CTA 128x128, 256 threads, 8 warps (2x4), warp tile 64x32, BK=32.
// MODE 0: C=AB+b ; 1: relu ; 2: relu(AB+b+res) (res may alias C)
// ============================================================
#define OFF_AH   0
#define OFF_AL   10240
#define OFF_ST   20480
#define ST_BYTES 38912      // 18432 (Araw) + 10240 (Bh) + 10240 (Bl)
#define ST_AR    0
#define ST_BH    18432
#define ST_BL    28672
#define TG_SMEM_BYTES 98304

template <int MODE>
__global__ __launch_bounds__(256) void tgemm_kernel(
    const float* __restrict__ A,
    const __nv_bfloat16* __restrict__ Bh, const __nv_bfloat16* __restrict__ Bl,
    const float* __restrict__ bias, float* C, const float* res, int M, int K)
{
    extern __shared__ char smc[];

    const int tid = threadIdx.x;
    const int lane = tid & 31, wid = tid >> 5;
    const int warp_m = wid >> 2, warp_n = wid & 3;   // 2 x 4 warp grid
    const int m0 = blockIdx.x * 128, n0 = blockIdx.y * 128;

    // convert coords: thread -> (row, k-half)
    const int lm  = tid >> 1;
    const int lkh = (tid & 1) * 16;

    // ldmatrix per-lane element coords
    const int a_r = lane & 15;
    const int a_c = (lane >> 4) << 3;
    const int b_r = ((lane >> 4) << 3) + (lane & 7);
    const int b_c = ((lane >> 3) & 1) << 3;

    const uint32_t u0 = (uint32_t)__cvta_generic_to_shared(smc);

    // issue one K-tile's async loads into staging buffer (kt&1)
    auto issue_tile = [&](int kt) {
        const int buf = kt & 1;
        const int k0 = kt << 5;
        const uint32_t st = u0 + OFF_ST + buf * ST_BYTES;
        // A raw fp32: 128 rows x 128B, rows padded to 144B; 1024 chunks, 4/thread
#pragma unroll
        for (int i = 0; i < 4; i++) {
            int id = tid + i * 256;
            int row = id >> 3, c = id & 7;
            int gm = m0 + row;
            cpa16(st + ST_AR + row * 144 + c * 16,
                  A + (size_t)gm * K + k0 + c * 4,
                  gm < M ? 16 : 0);
        }
        // B hi/lo bf16: 128 rows x 64B data in 80B rows; 512 chunks each, 2/thread
#pragma unroll
        for (int i = 0; i < 2; i++) {
            int id = tid + i * 256;
            int row = id >> 2, c = id & 3;
            size_t go = (size_t)(n0 + row) * K + k0 + c * 8;
            cpa16(st + ST_BH + row * 80 + c * 16, Bh + go, 16);
            cpa16(st + ST_BL + row * 80 + c * 16, Bl + go, 16);
        }
        cpa_commit();
    };

    float acc[4][4][4];
#pragma unroll
    for (int i = 0; i < 4; i++)
#pragma unroll
        for (int j = 0; j < 4; j++)
#pragma unroll
            for (int q = 0; q < 4; q++) acc[i][j][q] = 0.f;

    const int ntiles = K >> 5;
    issue_tile(0);
    if (ntiles > 1) issue_tile(1);

    for (int kt = 0; kt < ntiles; kt++) {
        const int buf = kt & 1;
        // wait until tile kt is complete (one younger group may stay in flight)
        if (kt + 1 < ntiles) {
            asm volatile("cp.async.wait_group 1;" ::: "memory");
        } else {
            asm volatile("cp.async.wait_group 0;" ::: "memory");
        }
        __syncthreads();   // staging[buf] visible to all threads

        // ---- convert A raw fp32 -> Ah/Al bf16 (smem -> smem) ----
        {
            const float* ar = reinterpret_cast<const float*>(
                smc + OFF_ST + buf * ST_BYTES + ST_AR) + lm * 36 + lkh;
            uint32_t* dh = reinterpret_cast<uint32_t*>(
                smc + OFF_AH + (lm * 40 + lkh) * 2);
            uint32_t* dl = reinterpret_cast<uint32_t*>(
                smc + OFF_AL + (lm * 40 + lkh) * 2);
            uint32_t hh[8], ll[8];
#pragma unroll
            for (int j = 0; j < 4; j++) {
                float4 v = *reinterpret_cast<const float4*>(ar + j * 4);
                split2(v.x, v.y, hh[2 * j],     ll[2 * j]);
                split2(v.z, v.w, hh[2 * j + 1], ll[2 * j + 1]);
            }
            *reinterpret_cast<uint4*>(dh)     = make_uint4(hh[0], hh[1], hh[2], hh[3]);
            *reinterpret_cast<uint4*>(dh + 4) = make_uint4(hh[4], hh[5], hh[6], hh[7]);
            *reinterpret_cast<uint4*>(dl)     = make_uint4(ll[0], ll[1], ll[2], ll[3]);
            *reinterpret_cast<uint4*>(dl + 4) = make_uint4(ll[4], ll[5], ll[6], ll[7]);
        }
        __syncthreads();

        const uint32_t uAh = u0 + OFF_AH;
        const uint32_t uAl = u0 + OFF_AL;
        const uint32_t uBh = u0 + OFF_ST + buf * ST_BYTES + ST_BH;
        const uint32_t uBl = u0 + OFF_ST + buf * ST_BYTES + ST_BL;

#pragma unroll
        for (int ks = 0; ks < 2; ks++) {
            uint32_t ah[4][4], al[4][4], bh[4][2], bl[4][2];
#pragma unroll
            for (int mt = 0; mt < 4; mt++) {
                int r = warp_m * 64 + mt * 16 + a_r;
                int c = ks * 16 + a_c;
                uint32_t off = (uint32_t)(r * 40 + c) * 2;
                ldsm_x4(ah[mt][0], ah[mt][1], ah[mt][2], ah[mt][3], uAh + off);
                ldsm_x4(al[mt][0], al[mt][1], al[mt][2], al[mt][3], uAl + off);
            }
#pragma unroll
            for (int np = 0; np < 2; np++) {
                int r = warp_n * 32 + np * 16 + b_r;
                int c = ks * 16 + b_c;
                uint32_t off = (uint32_t)(r * 40 + c) * 2;
                uint32_t r0, r1, r2, r3;
                ldsm_x4(r0, r1, r2, r3, uBh + off);
                bh[2 * np][0] = r0; bh[2 * np][1] = r1;
                bh[2 * np + 1][0] = r2; bh[2 * np + 1][1] = r3;
                ldsm_x4(r0, r1, r2, r3, uBl + off);
                bl[2 * np][0] = r0; bl[2 * np][1] = r1;
                bl[2 * np + 1][0] = r2; bl[2 * np + 1][1] = r3;
            }
#pragma unroll
            for (int mt = 0; mt < 4; mt++)
#pragma unroll
                for (int nt = 0; nt < 4; nt++) {
                    mma16816(acc[mt][nt], ah[mt], bh[nt]);
                    mma16816(acc[mt][nt], ah[mt], bl[nt]);
                    mma16816(acc[mt][nt], al[mt], bh[nt]);
                }
        }

        // all warps done reading staging[buf] before tile kt+2 overwrites it
        __syncthreads();
        if (kt + 2 < ntiles) issue_tile(kt + 2);
    }

    // ---- epilogue ----
#pragma unroll
    for (int nt = 0; nt < 4; nt++) {
        const int gn = n0 + warp_n * 32 + nt * 8 + (lane & 3) * 2;
        const float b0 = bias[gn], b1 = bias[gn + 1];
#pragma unroll
        for (int mt = 0; mt < 4; mt++) {
            const int gm = m0 + warp_m * 64 + mt * 16 + (lane >> 2);
#pragma unroll
            for (int half = 0; half < 2; half++) {
                const int r = gm + half * 8;
                if (r < M) {
                    float x0 = acc[mt][nt][2 * half]     + b0;
                    float x1 = acc[mt][nt][2 * half + 1] + b1;
                    size_t base = (size_t)r * 256 + gn;
                    if (MODE == 2) { x0 += res[base]; x1 += res[base + 1]; }
                    if (MODE >= 1) { x0 = fmaxf(x0, 0.f); x1 = fmaxf(x1, 0.f); }
                    *reinterpret_cast<float2*>(&C[base]) = make_float2(x0, x1);
                }
            }
        }
    }
}

// ============================================================
// message + scatter: aggr[dst] += relu(h[src] + e), warp per edge
// ============================================================
__global__ __launch_bounds__(256) void message_kernel(
    const float* __restrict__ h, const float* __restrict__ e,
    float* __restrict__ aggr)
{
    int warp = (blockIdx.x * blockDim.x + threadIdx.x) >> 5;
    int lane = threadIdx.x & 31;
    if (warp >= NE) return;
    int s = g_src[warp];
    int d = g_dst[warp];
    const float4* hs = reinterpret_cast<const float4*>(h + (size_t)s * DH);
    const float4* es = reinterpret_cast<const float4*>(e + (size_t)warp * DH);
    float* ad = aggr + (size_t)d * DH;
#pragma unroll
    for (int i = 0; i < 2; i++) {
        int f = lane + i * 32;
        float4 hv = hs[f];
        float4 ev = es[f];
        float mx = fmaxf(hv.x + ev.x, 0.f);
        float my = fmaxf(hv.y + ev.y, 0.f);
        float mz = fmaxf(hv.z + ev.z, 0.f);
        float mw = fmaxf(hv.w + ev.w, 0.f);
        asm volatile("red.global.add.v4.f32 [%0], {%1,%2,%3,%4};"
                     :: "l"(ad + (size_t)f * 4), "f"(mx), "f"(my), "f"(mz), "f"(mw)
                     : "memory");
    }
}

__global__ void init_z_kernel(const float* __restrict__ h, const float* __restrict__ eps,
                              float* __restrict__ aggr)
{
    size_t i = (size_t)blockIdx.x * blockDim.x + threadIdx.x;
    size_t n = (size_t)NN * DH / 4;
    if (i >= n) return;
    float s = 1.0f + *eps;
    float4 hv = reinterpret_cast<const float4*>(h)[i];
    reinterpret_cast<float4*>(aggr)[i] =
        make_float4(s * hv.x, s * hv.y, s * hv.z, s * hv.w);
}

__global__ void zero_pc_kernel(float* __restrict__ pool, float* __restrict__ cnt)
{
    int i = blockIdx.x * blockDim.x + threadIdx.x;
    if (i < NG * DH) pool[i] = 0.f;
    if (i < NG) cnt[i] = 0.f;
}

// ---- pooling: batch is sorted; run-length accumulate, few atomics ----
__global__ __launch_bounds__(256) void pool_kernel(
    const float* __restrict__ h, float* __restrict__ pool, float* __restrict__ cnt)
{
    const int f = threadIdx.x;
    int start = blockIdx.x * 100;
    int end = start + 100;
    if (end > NN) end = NN;
    if (start >= NN) return;
    float acc = 0.f;
    int cur = g_batch[start];
    int runlen = 0;
    for (int i = start; i < end; i++) {
        int b = g_batch[i];
        if (b != cur) {
            atomicAdd(&pool[cur * DH + f], acc);
            if (f == 0) atomicAdd(&cnt[cur], (float)runlen);
            acc = 0.f; runlen = 0; cur = b;
        }
        acc += h[(size_t)i * DH + f];
        runlen++;
    }
    atomicAdd(&pool[cur * DH + f], acc);
    if (f == 0) atomicAdd(&cnt[cur], (float)runlen);
}

__global__ void root_kernel(int* __restrict__ root)
{
    int i = blockIdx.x * blockDim.x + threadIdx.x;
    if (i >= NN) return;
    int b = g_batch[i];
    if (i == 0 || g_batch[i - 1] != b) root[b] = i;
}

__global__ __launch_bounds__(256) void final_kernel(
    const float* __restrict__ h, const float* __restrict__ pool,
    const float* __restrict__ cnt, const int* __restrict__ root,
    const float* __restrict__ Wo, const float* __restrict__ bo,
    const float* __restrict__ alpha, float* __restrict__ out)
{
    __shared__ float vec[DH];
    int g = blockIdx.x;
    int t = threadIdx.x;
    float a = *alpha;
    vec[t] = pool[g * DH + t] / cnt[g] + a * h[(size_t)root[g] * DH + t];
    __syncthreads();
    float s = bo[t];
#pragma unroll 8
    for (int k = 0; k < DH; k++) s = fmaf(vec[k], Wo[k * DOUT + t], s);
    out[g * DOUT + t] = s;
}

// ============================================================
extern "C" void kernel_launch(void* const* d_in, const int* in_sizes, int n_in,
                              void* d_out, int out_size)
{
    const float* x    = (const float*)d_in[0];
    const float* ea   = (const float*)d_in[1];
    const float* Wn   = (const float*)d_in[2];
    const float* bn   = (const float*)d_in[3];
    const float* We   = (const float*)d_in[4];
    const float* be   = (const float*)d_in[5];
    const float* c1W1 = (const float*)d_in[6];
    const float* c1b1 = (const float*)d_in[7];
    const float* c1W2 = (const float*)d_in[8];
    const float* c1b2 = (const float*)d_in[9];
    const float* eps1 = (const float*)d_in[10];
    const float* c2W1 = (const float*)d_in[11];
    const float* c2b1 = (const float*)d_in[12];
    const float* c2W2 = (const float*)d_in[13];
    const float* c2b2 = (const float*)d_in[14];
    const float* eps2 = (const float*)d_in[15];
    const float* Wo   = (const float*)d_in[16];
    const float* bo   = (const float*)d_in[17];
    const float* alpha= (const float*)d_in[18];
    const void*  ei    = d_in[19];
    const void*  batch = d_in[20];
    float* out = (float*)d_out;

    float *ph, *pe, *pa, *pt, *ppool, *pcnt;
    int* proot;
    __nv_bfloat16 *pwh, *pwl;
    cudaGetSymbolAddress((void**)&ph, g_h);
    cudaGetSymbolAddress((void**)&pe, g_e);
    cudaGetSymbolAddress((void**)&pa, g_aggr);
    cudaGetSymbolAddress((void**)&pt, g_t);
    cudaGetSymbolAddress((void**)&ppool, g_pool);
    cudaGetSymbolAddress((void**)&pcnt, g_cnt);
    cudaGetSymbolAddress((void**)&proot, g_root);
    cudaGetSymbolAddress((void**)&pwh, g_whi);
    cudaGetSymbolAddress((void**)&pwl, g_wlo);

    cudaFuncSetAttribute(tgemm_kernel<0>, cudaFuncAttributeMaxDynamicSharedMemorySize, TG_SMEM_BYTES);
    cudaFuncSetAttribute(tgemm_kernel<1>, cudaFuncAttributeMaxDynamicSharedMemorySize, TG_SMEM_BYTES);
    cudaFuncSetAttribute(tgemm_kernel<2>, cudaFuncAttributeMaxDynamicSharedMemorySize, TG_SMEM_BYTES);

    const dim3 gridN((NN + 127) / 128, 2);
    const dim3 gridE((NE + 127) / 128, 2);
    const size_t nh4 = (size_t)NN * DH / 4;
    const int zblocks = (int)((nh4 + 255) / 256);

    // index dtype detection + conversion
    detect_kernel<<<1, 1024>>>((const unsigned*)ei);
    convert_idx_kernel<<<(NE + 255) / 256, 256>>>(ei, batch);

    // weight prep: transpose + hi/lo split
    const int O_WN = 0, O_WE = 98304, O_11 = 196608, O_12 = 262144, O_21 = 327680, O_22 = 393216;
    prep_w_kernel<<<(DIN * 256 + 255) / 256, 256>>>(Wn,   DIN, O_WN);
    prep_w_kernel<<<(DIN * 256 + 255) / 256, 256>>>(We,   DIN, O_WE);
    prep_w_kernel<<<(DH  * 256 + 255) / 256, 256>>>(c1W1, DH,  O_11);
    prep_w_kernel<<<(DH  * 256 + 255) / 256, 256>>>(c1W2, DH,  O_12);
    prep_w_kernel<<<(DH  * 256 + 255) / 256, 256>>>(c2W1, DH,  O_21);
    prep_w_kernel<<<(DH  * 256 + 255) / 256, 256>>>(c2W2, DH,  O_22);

    // projections (tensor cores via mma.sync)
    tgemm_kernel<0><<<gridN, 256, TG_SMEM_BYTES>>>(x,  pwh + O_WN, pwl + O_WN, bn, ph, nullptr, NN, DIN);
    tgemm_kernel<0><<<gridE, 256, TG_SMEM_BYTES>>>(ea, pwh + O_WE, pwl + O_WE, be, pe, nullptr, NE, DIN);

    // two GINE layers
    for (int layer = 0; layer < 2; layer++) {
        const float* b1 = layer ? c2b1 : c1b1;
        const float* b2 = layer ? c2b2 : c1b2;
        const float* ep = layer ? eps2 : eps1;
        const int o1 = layer ? O_21 : O_11;
        const int o2 = layer ? O_22 : O_12;

        init_z_kernel<<<zblocks, 256>>>(ph, ep, pa);
        message_kernel<<<(NE * 32 + 255) / 256, 256>>>(ph, pe, pa);
        tgemm_kernel<1><<<gridN, 256, TG_SMEM_BYTES>>>(pa, pwh + o1, pwl + o1, b1, pt, nullptr, NN, DH);
        tgemm_kernel<2><<<gridN, 256, TG_SMEM_BYTES>>>(pt, pwh + o2, pwl + o2, b2, ph, ph, NN, DH);
    }

    // pooling + head
    zero_pc_kernel<<<(NG * DH + 255) / 256, 256>>>(ppool, pcnt);
    pool_kernel<<<(NN + 99) / 100, 256>>>(ph, ppool, pcnt);
    root_kernel<<<(NN + 255) / 256, 256>>>(proot);
    final_kernel<<<NG, 256>>>(ph, ppool, pcnt, proot, Wo, bo, alpha, out);
}

// round 17
// speedup vs baseline: 1.2248x; 1.0820x over previous
#include <cuda_runtime.h>
#include <cuda_bf16.h>
#include <cstdint>

#define NN 50000
#define NE 312500
#define NG 50
#define DIN 384
#define DH 256
#define DOUT 256

// ---- scratch (allocation-free: __device__ globals) ----
__device__ float g_h[(size_t)NN * DH];
__device__ float g_e[(size_t)NE * DH];
__device__ float g_aggr[(size_t)NN * DH];
__device__ float g_t[(size_t)NN * DH];
__device__ float g_pool[NG * DH];
__device__ float g_cnt[NG];
__device__ int   g_root[NG];
__device__ int   g_src[NE];
__device__ int   g_dst[NE];
__device__ int   g_batch[NN];
__device__ int   g_is64;

// transposed + hi/lo-split weights: [N=256, K] bf16, K-major rows
#define WT_TOTAL 458752
__device__ __nv_bfloat16 g_whi[WT_TOTAL];
__device__ __nv_bfloat16 g_wlo[WT_TOTAL];

// ============================================================
// baseline-PTX tensor helpers (sm_80 features; OK at compute_103)
// ============================================================
__device__ __forceinline__ void ldsm_x4(uint32_t& r0, uint32_t& r1, uint32_t& r2, uint32_t& r3,
                                        uint32_t addr) {
    asm volatile("ldmatrix.sync.aligned.m8n8.x4.shared.b16 {%0,%1,%2,%3}, [%4];"
                 : "=r"(r0), "=r"(r1), "=r"(r2), "=r"(r3) : "r"(addr));
}
__device__ __forceinline__ void mma16816(float* c, const uint32_t* a, const uint32_t* b) {
    asm volatile(
        "mma.sync.aligned.m16n8k16.row.col.f32.bf16.bf16.f32 "
        "{%0,%1,%2,%3}, {%4,%5,%6,%7}, {%8,%9}, {%0,%1,%2,%3};"
        : "+f"(c[0]), "+f"(c[1]), "+f"(c[2]), "+f"(c[3])
        : "r"(a[0]), "r"(a[1]), "r"(a[2]), "r"(a[3]), "r"(b[0]), "r"(b[1]));
}
__device__ __forceinline__ void split2(float a, float b, uint32_t& hi, uint32_t& lo) {
    __nv_bfloat16 ha = __float2bfloat16(a), hb = __float2bfloat16(b);
    float ra = a - __bfloat162float(ha);
    float rb = b - __bfloat162float(hb);
    hi = (uint32_t)__bfloat16_as_ushort(ha) | ((uint32_t)__bfloat16_as_ushort(hb) << 16);
    lo = (uint32_t)__bfloat16_as_ushort(__float2bfloat16(ra)) |
         ((uint32_t)__bfloat16_as_ushort(__float2bfloat16(rb)) << 16);
}

// ============================================================
// dtype detection for int64-vs-int32 index buffers
// ============================================================
__global__ __launch_bounds__(1024) void detect_kernel(const unsigned* __restrict__ w)
{
    __shared__ unsigned red[32];
    unsigned acc = 0;
    for (int i = threadIdx.x; i < NE; i += 1024)
        acc |= w[2 * i + 1];
#pragma unroll
    for (int o = 16; o > 0; o >>= 1) acc |= __shfl_xor_sync(0xffffffffu, acc, o);
    if ((threadIdx.x & 31) == 0) red[threadIdx.x >> 5] = acc;
    __syncthreads();
    if (threadIdx.x < 32) {
        unsigned v = red[threadIdx.x];
#pragma unroll
        for (int o = 16; o > 0; o >>= 1) v |= __shfl_xor_sync(0xffffffffu, v, o);
        if (threadIdx.x == 0) g_is64 = (v == 0u) ? 1 : 0;
    }
}

__global__ void convert_idx_kernel(const void* __restrict__ ei, const void* __restrict__ batch)
{
    int i = blockIdx.x * blockDim.x + threadIdx.x;
    const int is64 = g_is64;
    if (i < NE) {
        long long s, d;
        if (is64) {
            s = ((const long long*)ei)[i];
            d = ((const long long*)ei)[NE + i];
        } else {
            s = ((const int*)ei)[i];
            d = ((const int*)ei)[NE + i];
        }
        g_src[i] = (int)min((long long)(NN - 1), max(0LL, s));
        g_dst[i] = (int)min((long long)(NN - 1), max(0LL, d));
    }
    if (i < NN) {
        long long b = is64 ? ((const long long*)batch)[i] : (long long)((const int*)batch)[i];
        g_batch[i] = (int)min((long long)(NG - 1), max(0LL, b));
    }
}

// ---- weight prep: W[K,256] fp32 -> Wt hi/lo [256,K] bf16 ----
__global__ void prep_w_kernel(const float* __restrict__ W, int K, int off)
{
    int idx = blockIdx.x * blockDim.x + threadIdx.x;
    if (idx >= K * 256) return;
    int k = idx >> 8, n = idx & 255;
    float w = W[idx];
    __nv_bfloat16 h = __float2bfloat16(w);
    float r = w - __bfloat162float(h);
    g_whi[off + n * K + k] = h;
    g_wlo[off + n * K + k] = __float2bfloat16(r);
}

// ============================================================
// bf16x2-split mma.sync GEMM: C[M,256] = epi(A[M,K] @ W[K,256] + bias)
// C ≈ Ahi·Bhi + Ahi·Blo + Alo·Bhi  (fp32 accum)
// Synchronous single-buffered tiles (empirically fastest schedule);
// __launch_bounds__(256,2) caps regs at 128 for 2 CTAs/SM, and the
// inner loop holds only one B fragment pair at a time to fit.
// CTA 128x128, 256 threads, 8 warps (2x4), warp tile 64x32, BK=32.
// MODE 0: C=AB+b ; 1: relu ; 2: relu(AB+b+res) (res may alias C)
// ============================================================
template <int MODE>
__global__ __launch_bounds__(256, 2) void tgemm_kernel(
    const float* __restrict__ A,
    const __nv_bfloat16* __restrict__ Bh, const __nv_bfloat16* __restrict__ Bl,
    const float* __restrict__ bias, float* C, const float* res, int M, int K)
{
    __shared__ __nv_bfloat16 sAh[128][40];
    __shared__ __nv_bfloat16 sAl[128][40];
    __shared__ __nv_bfloat16 sBh[128][40];
    __shared__ __nv_bfloat16 sBl[128][40];

    const int tid = threadIdx.x;
    const int lane = tid & 31, wid = tid >> 5;
    const int warp_m = wid >> 2, warp_n = wid & 3;   // 2 x 4 warp grid
    const int m0 = blockIdx.x * 128, n0 = blockIdx.y * 128;

    // loader coords: thread -> (row, k-half)
    const int lm  = tid >> 1;
    const int lkh = (tid & 1) * 16;

    // ldmatrix per-lane element coords
    const int a_r = lane & 15;
    const int a_c = (lane >> 4) << 3;
    const int b_r = ((lane >> 4) << 3) + (lane & 7);
    const int b_c = ((lane >> 3) & 1) << 3;

    const uint32_t uAh = (uint32_t)__cvta_generic_to_shared(&sAh[0][0]);
    const uint32_t uAl = (uint32_t)__cvta_generic_to_shared(&sAl[0][0]);
    const uint32_t uBh = (uint32_t)__cvta_generic_to_shared(&sBh[0][0]);
    const uint32_t uBl = (uint32_t)__cvta_generic_to_shared(&sBl[0][0]);

    float acc[4][4][4];
#pragma unroll
    for (int i = 0; i < 4; i++)
#pragma unroll
        for (int j = 0; j < 4; j++)
#pragma unroll
            for (int q = 0; q < 4; q++) acc[i][j][q] = 0.f;

    for (int k0 = 0; k0 < K; k0 += 32) {
        // ---- load + split A: 16 fp32 per thread ----
        {
            const int gm = m0 + lm;
            uint32_t hh[8], ll[8];
            if (gm < M) {
                const float* ap = A + (size_t)gm * K + k0 + lkh;
#pragma unroll
                for (int j = 0; j < 4; j++) {
                    float4 v = *reinterpret_cast<const float4*>(ap + j * 4);
                    split2(v.x, v.y, hh[2 * j],     ll[2 * j]);
                    split2(v.z, v.w, hh[2 * j + 1], ll[2 * j + 1]);
                }
            } else {
#pragma unroll
                for (int j = 0; j < 8; j++) { hh[j] = 0u; ll[j] = 0u; }
            }
            uint32_t* dh = reinterpret_cast<uint32_t*>(&sAh[lm][lkh]);
            uint32_t* dl = reinterpret_cast<uint32_t*>(&sAl[lm][lkh]);
            *reinterpret_cast<uint4*>(dh)     = make_uint4(hh[0], hh[1], hh[2], hh[3]);
            *reinterpret_cast<uint4*>(dh + 4) = make_uint4(hh[4], hh[5], hh[6], hh[7]);
            *reinterpret_cast<uint4*>(dl)     = make_uint4(ll[0], ll[1], ll[2], ll[3]);
            *reinterpret_cast<uint4*>(dl + 4) = make_uint4(ll[4], ll[5], ll[6], ll[7]);
        }
        // ---- load B hi/lo: 16 bf16 per thread each ----
        {
            const size_t go = (size_t)(n0 + lm) * K + k0 + lkh;
            uint4 v0 = *reinterpret_cast<const uint4*>(Bh + go);
            uint4 v1 = *reinterpret_cast<const uint4*>(Bh + go + 8);
            uint4 w0 = *reinterpret_cast<const uint4*>(Bl + go);
            uint4 w1 = *reinterpret_cast<const uint4*>(Bl + go + 8);
            *reinterpret_cast<uint4*>(&sBh[lm][lkh])     = v0;
            *reinterpret_cast<uint4*>(&sBh[lm][lkh + 8]) = v1;
            *reinterpret_cast<uint4*>(&sBl[lm][lkh])     = w0;
            *reinterpret_cast<uint4*>(&sBl[lm][lkh + 8]) = w1;
        }
        __syncthreads();

#pragma unroll
        for (int ks = 0; ks < 2; ks++) {
            // A fragments for all 4 m-tiles (32 regs held)
            uint32_t ah[4][4], al[4][4];
#pragma unroll
            for (int mt = 0; mt < 4; mt++) {
                int r = warp_m * 64 + mt * 16 + a_r;
                int c = ks * 16 + a_c;
                uint32_t off = (uint32_t)(r * 40 + c) * 2;
                ldsm_x4(ah[mt][0], ah[mt][1], ah[mt][2], ah[mt][3], uAh + off);
                ldsm_x4(al[mt][0], al[mt][1], al[mt][2], al[mt][3], uAl + off);
            }
            // B fragments: one n16 pair at a time (8 regs transient)
#pragma unroll
            for (int np = 0; np < 2; np++) {
                int r = warp_n * 32 + np * 16 + b_r;
                int c = ks * 16 + b_c;
                uint32_t off = (uint32_t)(r * 40 + c) * 2;
                uint32_t bh[4], bl[4];
                ldsm_x4(bh[0], bh[1], bh[2], bh[3], uBh + off);
                ldsm_x4(bl[0], bl[1], bl[2], bl[3], uBl + off);
#pragma unroll
                for (int mt = 0; mt < 4; mt++) {
                    mma16816(acc[mt][2 * np],     ah[mt], bh);
                    mma16816(acc[mt][2 * np],     ah[mt], bl);
                    mma16816(acc[mt][2 * np],     al[mt], bh);
                    mma16816(acc[mt][2 * np + 1], ah[mt], bh + 2);
                    mma16816(acc[mt][2 * np + 1], ah[mt], bl + 2);
                    mma16816(acc[mt][2 * np + 1], al[mt], bh + 2);
                }
            }
        }
        __syncthreads();
    }

    // ---- epilogue ----
#pragma unroll
    for (int nt = 0; nt < 4; nt++) {
        const int gn = n0 + warp_n * 32 + nt * 8 + (lane & 3) * 2;
        const float b0 = bias[gn], b1 = bias[gn + 1];
#pragma unroll
        for (int mt = 0; mt < 4; mt++) {
            const int gm = m0 + warp_m * 64 + mt * 16 + (lane >> 2);
#pragma unroll
            for (int half = 0; half < 2; half++) {
                const int r = gm + half * 8;
                if (r < M) {
                    float x0 = acc[mt][nt][2 * half]     + b0;
                    float x1 = acc[mt][nt][2 * half + 1] + b1;
                    size_t base = (size_t)r * 256 + gn;
                    if (MODE == 2) { x0 += res[base]; x1 += res[base + 1]; }
                    if (MODE >= 1) { x0 = fmaxf(x0, 0.f); x1 = fmaxf(x1, 0.f); }
                    *reinterpret_cast<float2*>(&C[base]) = make_float2(x0, x1);
                }
            }
        }
    }
}

// ============================================================
// message + scatter: aggr[dst] += relu(h[src] + e), warp per edge
// ============================================================
__global__ __launch_bounds__(256) void message_kernel(
    const float* __restrict__ h, const float* __restrict__ e,
    float* __restrict__ aggr)
{
    int warp = (blockIdx.x * blockDim.x + threadIdx.x) >> 5;
    int lane = threadIdx.x & 31;
    if (warp >= NE) return;
    int s = g_src[warp];
    int d = g_dst[warp];
    const float4* hs = reinterpret_cast<const float4*>(h + (size_t)s * DH);
    const float4* es = reinterpret_cast<const float4*>(e + (size_t)warp * DH);
    float* ad = aggr + (size_t)d * DH;
#pragma unroll
    for (int i = 0; i < 2; i++) {
        int f = lane + i * 32;
        float4 hv = hs[f];
        float4 ev = es[f];
        float mx = fmaxf(hv.x + ev.x, 0.f);
        float my = fmaxf(hv.y + ev.y, 0.f);
        float mz = fmaxf(hv.z + ev.z, 0.f);
        float mw = fmaxf(hv.w + ev.w, 0.f);
        asm volatile("red.global.add.v4.f32 [%0], {%1,%2,%3,%4};"
                     :: "l"(ad + (size_t)f * 4), "f"(mx), "f"(my), "f"(mz), "f"(mw)
                     : "memory");
    }
}

__global__ void init_z_kernel(const float* __restrict__ h, const float* __restrict__ eps,
                              float* __restrict__ aggr)
{
    size_t i = (size_t)blockIdx.x * blockDim.x + threadIdx.x;
    size_t n = (size_t)NN * DH / 4;
    if (i >= n) return;
    float s = 1.0f + *eps;
    float4 hv = reinterpret_cast<const float4*>(h)[i];
    reinterpret_cast<float4*>(aggr)[i] =
        make_float4(s * hv.x, s * hv.y, s * hv.z, s * hv.w);
}

__global__ void zero_pc_kernel(float* __restrict__ pool, float* __restrict__ cnt)
{
    int i = blockIdx.x * blockDim.x + threadIdx.x;
    if (i < NG * DH) pool[i] = 0.f;
    if (i < NG) cnt[i] = 0.f;
}

// ---- pooling: batch is sorted; run-length accumulate, few atomics ----
__global__ __launch_bounds__(256) void pool_kernel(
    const float* __restrict__ h, float* __restrict__ pool, float* __restrict__ cnt)
{
    const int f = threadIdx.x;
    int start = blockIdx.x * 100;
    int end = start + 100;
    if (end > NN) end = NN;
    if (start >= NN) return;
    float acc = 0.f;
    int cur = g_batch[start];
    int runlen = 0;
    for (int i = start; i < end; i++) {
        int b = g_batch[i];
        if (b != cur) {
            atomicAdd(&pool[cur * DH + f], acc);
            if (f == 0) atomicAdd(&cnt[cur], (float)runlen);
            acc = 0.f; runlen = 0; cur = b;
        }
        acc += h[(size_t)i * DH + f];
        runlen++;
    }
    atomicAdd(&pool[cur * DH + f], acc);
    if (f == 0) atomicAdd(&cnt[cur], (float)runlen);
}

__global__ void root_kernel(int* __restrict__ root)
{
    int i = blockIdx.x * blockDim.x + threadIdx.x;
    if (i >= NN) return;
    int b = g_batch[i];
    if (i == 0 || g_batch[i - 1] != b) root[b] = i;
}

__global__ __launch_bounds__(256) void final_kernel(
    const float* __restrict__ h, const float* __restrict__ pool,
    const float* __restrict__ cnt, const int* __restrict__ root,
    const float* __restrict__ Wo, const float* __restrict__ bo,
    const float* __restrict__ alpha, float* __restrict__ out)
{
    __shared__ float vec[DH];
    int g = blockIdx.x;
    int t = threadIdx.x;
    float a = *alpha;
    vec[t] = pool[g * DH + t] / cnt[g] + a * h[(size_t)root[g] * DH + t];
    __syncthreads();
    float s = bo[t];
#pragma unroll 8
    for (int k = 0; k < DH; k++) s = fmaf(vec[k], Wo[k * DOUT + t], s);
    out[g * DOUT + t] = s;
}

// ============================================================
extern "C" void kernel_launch(void* const* d_in, const int* in_sizes, int n_in,
                              void* d_out, int out_size)
{
    const float* x    = (const float*)d_in[0];
    const float* ea   = (const float*)d_in[1];
    const float* Wn   = (const float*)d_in[2];
    const float* bn   = (const float*)d_in[3];
    const float* We   = (const float*)d_in[4];
    const float* be   = (const float*)d_in[5];
    const float* c1W1 = (const float*)d_in[6];
    const float* c1b1 = (const float*)d_in[7];
    const float* c1W2 = (const float*)d_in[8];
    const float* c1b2 = (const float*)d_in[9];
    const float* eps1 = (const float*)d_in[10];
    const float* c2W1 = (const float*)d_in[11];
    const float* c2b1 = (const float*)d_in[12];
    const float* c2W2 = (const float*)d_in[13];
    const float* c2b2 = (const float*)d_in[14];
    const float* eps2 = (const float*)d_in[15];
    const float* Wo   = (const float*)d_in[16];
    const float* bo   = (const float*)d_in[17];
    const float* alpha= (const float*)d_in[18];
    const void*  ei    = d_in[19];
    const void*  batch = d_in[20];
    float* out = (float*)d_out;

    float *ph, *pe, *pa, *pt, *ppool, *pcnt;
    int* proot;
    __nv_bfloat16 *pwh, *pwl;
    cudaGetSymbolAddress((void**)&ph, g_h);
    cudaGetSymbolAddress((void**)&pe, g_e);
    cudaGetSymbolAddress((void**)&pa, g_aggr);
    cudaGetSymbolAddress((void**)&pt, g_t);
    cudaGetSymbolAddress((void**)&ppool, g_pool);
    cudaGetSymbolAddress((void**)&pcnt, g_cnt);
    cudaGetSymbolAddress((void**)&proot, g_root);
    cudaGetSymbolAddress((void**)&pwh, g_whi);
    cudaGetSymbolAddress((void**)&pwl, g_wlo);

    const dim3 gridN((NN + 127) / 128, 2);
    const dim3 gridE((NE + 127) / 128, 2);
    const size_t nh4 = (size_t)NN * DH / 4;
    const int zblocks = (int)((nh4 + 255) / 256);

    // index dtype detection + conversion
    detect_kernel<<<1, 1024>>>((const unsigned*)ei);
    convert_idx_kernel<<<(NE + 255) / 256, 256>>>(ei, batch);

    // weight prep: transpose + hi/lo split
    const int O_WN = 0, O_WE = 98304, O_11 = 196608, O_12 = 262144, O_21 = 327680, O_22 = 393216;
    prep_w_kernel<<<(DIN * 256 + 255) / 256, 256>>>(Wn,   DIN, O_WN);
    prep_w_kernel<<<(DIN * 256 + 255) / 256, 256>>>(We,   DIN, O_WE);
    prep_w_kernel<<<(DH  * 256 + 255) / 256, 256>>>(c1W1, DH,  O_11);
    prep_w_kernel<<<(DH  * 256 + 255) / 256, 256>>>(c1W2, DH,  O_12);
    prep_w_kernel<<<(DH  * 256 + 255) / 256, 256>>>(c2W1, DH,  O_21);
    prep_w_kernel<<<(DH  * 256 + 255) / 256, 256>>>(c2W2, DH,  O_22);

    // projections (tensor cores via mma.sync)
    tgemm_kernel<0><<<gridN, 256>>>(x,  pwh + O_WN, pwl + O_WN, bn, ph, nullptr, NN, DIN);
    tgemm_kernel<0><<<gridE, 256>>>(ea, pwh + O_WE, pwl + O_WE, be, pe, nullptr, NE, DIN);

    // two GINE layers
    for (int layer = 0; layer < 2; layer++) {
        const float* b1 = layer ? c2b1 : c1b1;
        const float* b2 = layer ? c2b2 : c1b2;
        const float* ep = layer ? eps2 : eps1;
        const int o1 = layer ? O_21 : O_11;
        const int o2 = layer ? O_22 : O_12;

        init_z_kernel<<<zblocks, 256>>>(ph, ep, pa);
        message_kernel<<<(NE * 32 + 255) / 256, 256>>>(ph, pe, pa);
        tgemm_kernel<1><<<gridN, 256>>>(pa, pwh + o1, pwl + o1, b1, pt, nullptr, NN, DH);
        tgemm_kernel<2><<<gridN, 256>>>(pt, pwh + o2, pwl + o2, b2, ph, ph, NN, DH);
    }

    // pooling + head
    zero_pc_kernel<<<(NG * DH + 255) / 256, 256>>>(ppool, pcnt);
    pool_kernel<<<(NN + 99) / 100, 256>>>(ph, ppool, pcnt);
    root_kernel<<<(NN + 255) / 256, 256>>>(proot);
    final_kernel<<<NG, 256>>>(ph, ppool, pcnt, proot, Wo, bo, alpha, out);
}